// round 2
// baseline (speedup 1.0000x reference)
#include <cuda_runtime.h>

// Beamform_1649267442279 — GB300 sm_103a — R2: smem-staged fully-coalesced I/O
//
// Semantics (from reference): per channel s, blocks of 20 complex samples
// (40 floats). Block b, row r (0..3), col c (0..4):
//   re[r,c] = in_s[40b + 10r + 2c],  im[r,c] = in_s[40b + 10r + 2c + 1]
//   out[(s*Bc+b)*10 + c]     = sum_r br[r]*re - bi[r]*im
//   out[(s*Bc+b)*10 + 5 + c] = sum_r bi[r]*re + br[r]*im
// with br[r]=bf[2r], bi[r]=bf[2r+1].
//
// R2 layout: 160 threads/CTA, 32 beam-blocks/CTA (1280 floats in, 320 out).
//  phase 1: 2x LDG.128/thread, perfectly coalesced -> smem
//  phase 2: strided float2 reads from smem (cheap), complex-weighted sum
//  phase 3: outputs staged in smem, flushed as 80 coalesced STG.128

constexpr int BLK_PER_CTA = 32;           // beam blocks per CTA
constexpr int THREADS     = 160;          // 5 threads per beam block
constexpr int IN_FLOATS   = BLK_PER_CTA * 40;   // 1280
constexpr int OUT_FLOATS  = BLK_PER_CTA * 10;   // 320

__global__ void __launch_bounds__(THREADS)
beamform_kernel(const float* __restrict__ in0,
                const float* __restrict__ in1,
                const float* __restrict__ in2,
                const float* __restrict__ in3,
                const float* __restrict__ bf,
                float* __restrict__ out,
                int blocks_per_ch, int n_floats_per_ch)
{
    __shared__ float s_in[IN_FLOATS];
    __shared__ float s_out[OUT_FLOATS];

    const int t  = threadIdx.x;
    const int ch = blockIdx.y;
    const float* __restrict__ in =
        (ch == 0) ? in0 : (ch == 1) ? in1 : (ch == 2) ? in2 : in3;

    // ---- phase 1: coalesced global -> smem (2x float4 per thread) ----
    const size_t f4_base = (size_t)blockIdx.x * (IN_FLOATS / 4);
    const float4* __restrict__ src = (const float4*)in + f4_base;
    float4* s4 = (float4*)s_in;
    const size_t n_f4 = (size_t)n_floats_per_ch / 4;

    if (f4_base + t < n_f4)            s4[t]           = __ldg(src + t);
    if (f4_base + t + THREADS < n_f4)  s4[t + THREADS] = __ldg(src + t + THREADS);
    __syncthreads();

    // ---- phase 2: compute (thread t -> local block b, col j) ----
    const int b = t / 5;
    const int j = t - b * 5;
    const int bb = blockIdx.x * BLK_PER_CTA + b;     // global block in channel

    const float4 w0 = __ldg((const float4*)bf);      // br0, bi0, br1, bi1
    const float4 w1 = __ldg((const float4*)bf + 1);  // br2, bi2, br3, bi3

    if (bb < blocks_per_ch) {
        const float2* p = (const float2*)(s_in + b * 40 + 2 * j);
        const float2 v0 = p[0];
        const float2 v1 = p[5];
        const float2 v2 = p[10];
        const float2 v3 = p[15];

        float re = w0.x * v0.x - w0.y * v0.y;
        float im = w0.y * v0.x + w0.x * v0.y;
        re += w0.z * v1.x - w0.w * v1.y;
        im += w0.w * v1.x + w0.z * v1.y;
        re += w1.x * v2.x - w1.y * v2.y;
        im += w1.y * v2.x + w1.x * v2.y;
        re += w1.z * v3.x - w1.w * v3.y;
        im += w1.w * v3.x + w1.z * v3.y;

        s_out[b * 10 + j]     = re;
        s_out[b * 10 + 5 + j] = im;
    }
    __syncthreads();

    // ---- phase 3: coalesced smem -> global (80 float4 stores) ----
    if (t < OUT_FLOATS / 4) {
        const size_t out_f4_base =
            ((size_t)ch * blocks_per_ch * 10) / 4 + (size_t)blockIdx.x * (OUT_FLOATS / 4);
        const size_t out_f4_end = ((size_t)(ch + 1) * blocks_per_ch * 10) / 4;
        if (out_f4_base + t < out_f4_end)
            ((float4*)out)[out_f4_base + t] = ((const float4*)s_out)[t];
    }
}

extern "C" void kernel_launch(void* const* d_in, const int* in_sizes, int n_in,
                              void* d_out, int out_size)
{
    const float* in0 = (const float*)d_in[0];
    const float* in1 = (const float*)d_in[1];
    const float* in2 = (const float*)d_in[2];
    const float* in3 = (const float*)d_in[3];
    const float* bf  = (const float*)d_in[4];
    float* out = (float*)d_out;

    const int N  = in_sizes[0];          // 20,000,000 floats / channel
    const int Bc = N / 40;               // 500,000 beam blocks per channel

    dim3 grid((Bc + BLK_PER_CTA - 1) / BLK_PER_CTA, 4);   // 15625 x 4
    beamform_kernel<<<grid, THREADS>>>(in0, in1, in2, in3, bf, out, Bc, N);
}

// round 3
// speedup vs baseline: 1.1246x; 1.1246x over previous
#include <cuda_runtime.h>

// Beamform_1649267442279 — GB300 sm_103a — R3: direct loads, 2 blocks/thread,
// front-batched MLP=8, streaming loads.
//
// Semantics: per channel s, blocks of 20 complex samples (40 floats).
// Block b, row r (0..3), col c (0..4):
//   re[r,c] = in_s[40b + 10r + 2c],  im[r,c] = in_s[40b + 10r + 2c + 1]
//   out[(s*Bc+b)*10 + c]     = sum_r br[r]*re - bi[r]*im
//   out[(s*Bc+b)*10 + 5 + c] = sum_r bi[r]*re + br[r]*im
// with br[r]=bf[2r], bi[r]=bf[2r+1].
//
// Thread (g, ch) handles col j of beam blocks 2B and 2B+1 where
// g = B*5 + j. All 8 float2 loads are independent and issued before any
// compute -> 8 outstanding LDG.64 per thread hides DRAM latency.

__device__ __forceinline__ float2 ldcs2(const float2* p) {
    return __ldcs(p);
}

__global__ void __launch_bounds__(256)
beamform_kernel(const float* __restrict__ in0,
                const float* __restrict__ in1,
                const float* __restrict__ in2,
                const float* __restrict__ in3,
                const float* __restrict__ bf,
                float* __restrict__ out,
                int pairs_per_ch,      // blocks_per_ch / 2
                int blocks_per_ch)
{
    const int g = blockIdx.x * blockDim.x + threadIdx.x;
    if (g >= pairs_per_ch * 5) return;

    const int ch = blockIdx.y;
    const float* __restrict__ in =
        (ch == 0) ? in0 : (ch == 1) ? in1 : (ch == 2) ? in2 : in3;

    const int B = g / 5;            // block pair index
    const int j = g - B * 5;        // column 0..4
    const int b0 = 2 * B;           // first beam block of the pair

    // ---- front-batched loads: 8 independent LDG.64 ----
    const float2* __restrict__ pA =
        (const float2*)(in + (size_t)b0 * 40 + 2 * j);
    const float2* __restrict__ pB = pA + 20;   // next beam block (+40 floats)

    const float2 a0 = ldcs2(pA + 0);
    const float2 a1 = ldcs2(pA + 5);
    const float2 a2 = ldcs2(pA + 10);
    const float2 a3 = ldcs2(pA + 15);
    const float2 c0 = ldcs2(pB + 0);
    const float2 c1 = ldcs2(pB + 5);
    const float2 c2 = ldcs2(pB + 10);
    const float2 c3 = ldcs2(pB + 15);

    // weights: uniform-address broadcast, L1-resident
    const float4 w0 = __ldg((const float4*)bf);      // br0, bi0, br1, bi1
    const float4 w1 = __ldg((const float4*)bf + 1);  // br2, bi2, br3, bi3

    float reA = w0.x * a0.x - w0.y * a0.y;
    float imA = w0.y * a0.x + w0.x * a0.y;
    reA += w0.z * a1.x - w0.w * a1.y;
    imA += w0.w * a1.x + w0.z * a1.y;
    reA += w1.x * a2.x - w1.y * a2.y;
    imA += w1.y * a2.x + w1.x * a2.y;
    reA += w1.z * a3.x - w1.w * a3.y;
    imA += w1.w * a3.x + w1.z * a3.y;

    float reB = w0.x * c0.x - w0.y * c0.y;
    float imB = w0.y * c0.x + w0.x * c0.y;
    reB += w0.z * c1.x - w0.w * c1.y;
    imB += w0.w * c1.x + w0.z * c1.y;
    reB += w1.x * c2.x - w1.y * c2.y;
    imB += w1.y * c2.x + w1.x * c2.y;
    reB += w1.z * c3.x - w1.w * c3.y;
    imB += w1.w * c3.x + w1.z * c3.y;

    const size_t ob = ((size_t)ch * blocks_per_ch + (size_t)b0) * 10;
    out[ob + j]          = reA;
    out[ob + 5 + j]      = imA;
    out[ob + 10 + j]     = reB;
    out[ob + 15 + j]     = imB;
}

extern "C" void kernel_launch(void* const* d_in, const int* in_sizes, int n_in,
                              void* d_out, int out_size)
{
    const float* in0 = (const float*)d_in[0];
    const float* in1 = (const float*)d_in[1];
    const float* in2 = (const float*)d_in[2];
    const float* in3 = (const float*)d_in[3];
    const float* bf  = (const float*)d_in[4];
    float* out = (float*)d_out;

    const int N  = in_sizes[0];          // 20,000,000 floats / channel
    const int Bc = N / 40;               // 500,000 beam blocks per channel
    const int Pc = Bc / 2;               // 250,000 block pairs per channel

    const int threads = 256;
    const int n_thr = Pc * 5;            // 1.25M threads per channel
    dim3 grid((n_thr + threads - 1) / threads, 4);

    beamform_kernel<<<grid, threads>>>(in0, in1, in2, in3, bf, out, Pc, Bc);
}

// round 4
// speedup vs baseline: 1.1339x; 1.0083x over previous
#include <cuda_runtime.h>

// Beamform_1649267442279 — GB300 sm_103a — R4: R3 structure (2 blocks/thread,
// front-batched MLP=8) with default-cached loads (revert __ldcs — evict-first
// broke the 4x per-line reuse across row loads and inflated L2 traffic).
//
// Semantics: per channel s, blocks of 20 complex samples (40 floats).
// Block b, row r (0..3), col c (0..4):
//   re[r,c] = in_s[40b + 10r + 2c],  im[r,c] = in_s[40b + 10r + 2c + 1]
//   out[(s*Bc+b)*10 + c]     = sum_r br[r]*re - bi[r]*im
//   out[(s*Bc+b)*10 + 5 + c] = sum_r bi[r]*re + br[r]*im
// with br[r]=bf[2r], bi[r]=bf[2r+1].

__global__ void __launch_bounds__(256)
beamform_kernel(const float* __restrict__ in0,
                const float* __restrict__ in1,
                const float* __restrict__ in2,
                const float* __restrict__ in3,
                const float* __restrict__ bf,
                float* __restrict__ out,
                int pairs_per_ch,      // blocks_per_ch / 2
                int blocks_per_ch)
{
    const int g = blockIdx.x * blockDim.x + threadIdx.x;
    if (g >= pairs_per_ch * 5) return;

    const int ch = blockIdx.y;
    const float* __restrict__ in =
        (ch == 0) ? in0 : (ch == 1) ? in1 : (ch == 2) ? in2 : in3;

    const int B = g / 5;            // block pair index
    const int j = g - B * 5;        // column 0..4
    const int b0 = 2 * B;           // first beam block of the pair

    // ---- front-batched loads: 8 independent LDG.64, default caching ----
    const float2* __restrict__ pA =
        (const float2*)(in + (size_t)b0 * 40 + 2 * j);
    const float2* __restrict__ pB = pA + 20;   // next beam block (+40 floats)

    const float2 a0 = __ldg(pA + 0);
    const float2 a1 = __ldg(pA + 5);
    const float2 a2 = __ldg(pA + 10);
    const float2 a3 = __ldg(pA + 15);
    const float2 c0 = __ldg(pB + 0);
    const float2 c1 = __ldg(pB + 5);
    const float2 c2 = __ldg(pB + 10);
    const float2 c3 = __ldg(pB + 15);

    // weights: uniform-address broadcast, L1-resident
    const float4 w0 = __ldg((const float4*)bf);      // br0, bi0, br1, bi1
    const float4 w1 = __ldg((const float4*)bf + 1);  // br2, bi2, br3, bi3

    float reA = w0.x * a0.x - w0.y * a0.y;
    float imA = w0.y * a0.x + w0.x * a0.y;
    reA += w0.z * a1.x - w0.w * a1.y;
    imA += w0.w * a1.x + w0.z * a1.y;
    reA += w1.x * a2.x - w1.y * a2.y;
    imA += w1.y * a2.x + w1.x * a2.y;
    reA += w1.z * a3.x - w1.w * a3.y;
    imA += w1.w * a3.x + w1.z * a3.y;

    float reB = w0.x * c0.x - w0.y * c0.y;
    float imB = w0.y * c0.x + w0.x * c0.y;
    reB += w0.z * c1.x - w0.w * c1.y;
    imB += w0.w * c1.x + w0.z * c1.y;
    reB += w1.x * c2.x - w1.y * c2.y;
    imB += w1.y * c2.x + w1.x * c2.y;
    reB += w1.z * c3.x - w1.w * c3.y;
    imB += w1.w * c3.x + w1.z * c3.y;

    const size_t ob = ((size_t)ch * blocks_per_ch + (size_t)b0) * 10;
    out[ob + j]          = reA;
    out[ob + 5 + j]      = imA;
    out[ob + 10 + j]     = reB;
    out[ob + 15 + j]     = imB;
}

extern "C" void kernel_launch(void* const* d_in, const int* in_sizes, int n_in,
                              void* d_out, int out_size)
{
    const float* in0 = (const float*)d_in[0];
    const float* in1 = (const float*)d_in[1];
    const float* in2 = (const float*)d_in[2];
    const float* in3 = (const float*)d_in[3];
    const float* bf  = (const float*)d_in[4];
    float* out = (float*)d_out;

    const int N  = in_sizes[0];          // 20,000,000 floats / channel
    const int Bc = N / 40;               // 500,000 beam blocks per channel
    const int Pc = Bc / 2;               // 250,000 block pairs per channel

    const int threads = 256;
    const int n_thr = Pc * 5;            // 1.25M threads per channel
    dim3 grid((n_thr + threads - 1) / threads, 4);

    beamform_kernel<<<grid, threads>>>(in0, in1, in2, in3, bf, out, Pc, Bc);
}

// round 5
// speedup vs baseline: 1.1990x; 1.0574x over previous
#include <cuda_runtime.h>

// Beamform_1649267442279 — GB300 sm_103a — R5: R1 mapping (compact 1KB warp
// windows) + MLP=8 via two FAR-APART blocks per thread (b and b + Bc/2).
// R4 showed adjacent-block pairing doubles the warp footprint per LDG and
// hurts L2; split-half pairing keeps each window identical to R1's.
//
// Semantics: per channel s, blocks of 20 complex samples (40 floats).
// Block b, row r (0..3), col c (0..4):
//   re[r,c] = in_s[40b + 10r + 2c],  im[r,c] = in_s[40b + 10r + 2c + 1]
//   out[(s*Bc+b)*10 + c]     = sum_r br[r]*re - bi[r]*im
//   out[(s*Bc+b)*10 + 5 + c] = sum_r bi[r]*re + br[r]*im
// with br[r]=bf[2r], bi[r]=bf[2r+1].

__global__ void __launch_bounds__(256)
beamform_kernel(const float* __restrict__ in0,
                const float* __restrict__ in1,
                const float* __restrict__ in2,
                const float* __restrict__ in3,
                const float* __restrict__ bf,
                float* __restrict__ out,
                int half_blocks,       // Bc / 2
                int blocks_per_ch)     // Bc
{
    const int g = blockIdx.x * blockDim.x + threadIdx.x;
    if (g >= half_blocks * 5) return;

    const int ch = blockIdx.y;
    const float* __restrict__ in =
        (ch == 0) ? in0 : (ch == 1) ? in1 : (ch == 2) ? in2 : in3;

    const int b = g / 5;            // block in first half
    const int j = g - b * 5;        // column 0..4

    // ---- front-batched loads: 8 independent LDG.64, two compact windows ----
    const float2* __restrict__ pA =
        (const float2*)(in + (size_t)b * 40 + 2 * j);
    const float2* __restrict__ pB = pA + (size_t)half_blocks * 20;  // +Bc/2 blocks

    const float2 a0 = __ldg(pA + 0);
    const float2 a1 = __ldg(pA + 5);
    const float2 a2 = __ldg(pA + 10);
    const float2 a3 = __ldg(pA + 15);
    const float2 c0 = __ldg(pB + 0);
    const float2 c1 = __ldg(pB + 5);
    const float2 c2 = __ldg(pB + 10);
    const float2 c3 = __ldg(pB + 15);

    // weights: uniform-address broadcast, L1-resident
    const float4 w0 = __ldg((const float4*)bf);      // br0, bi0, br1, bi1
    const float4 w1 = __ldg((const float4*)bf + 1);  // br2, bi2, br3, bi3

    float reA = w0.x * a0.x - w0.y * a0.y;
    float imA = w0.y * a0.x + w0.x * a0.y;
    reA += w0.z * a1.x - w0.w * a1.y;
    imA += w0.w * a1.x + w0.z * a1.y;
    reA += w1.x * a2.x - w1.y * a2.y;
    imA += w1.y * a2.x + w1.x * a2.y;
    reA += w1.z * a3.x - w1.w * a3.y;
    imA += w1.w * a3.x + w1.z * a3.y;

    float reB = w0.x * c0.x - w0.y * c0.y;
    float imB = w0.y * c0.x + w0.x * c0.y;
    reB += w0.z * c1.x - w0.w * c1.y;
    imB += w0.w * c1.x + w0.z * c1.y;
    reB += w1.x * c2.x - w1.y * c2.y;
    imB += w1.y * c2.x + w1.x * c2.y;
    reB += w1.z * c3.x - w1.w * c3.y;
    imB += w1.w * c3.x + w1.z * c3.y;

    const size_t obA = ((size_t)ch * blocks_per_ch + (size_t)b) * 10;
    const size_t obB = obA + (size_t)half_blocks * 10;
    out[obA + j]     = reA;
    out[obA + 5 + j] = imA;
    out[obB + j]     = reB;
    out[obB + 5 + j] = imB;
}

extern "C" void kernel_launch(void* const* d_in, const int* in_sizes, int n_in,
                              void* d_out, int out_size)
{
    const float* in0 = (const float*)d_in[0];
    const float* in1 = (const float*)d_in[1];
    const float* in2 = (const float*)d_in[2];
    const float* in3 = (const float*)d_in[3];
    const float* bf  = (const float*)d_in[4];
    float* out = (float*)d_out;

    const int N  = in_sizes[0];          // 20,000,000 floats / channel
    const int Bc = N / 40;               // 500,000 beam blocks per channel
    const int Hb = Bc / 2;               // 250,000 blocks in each half

    const int threads = 256;
    const int n_thr = Hb * 5;            // 1.25M threads per channel
    dim3 grid((n_thr + threads - 1) / threads, 4);

    beamform_kernel<<<grid, threads>>>(in0, in1, in2, in3, bf, out, Hb, Bc);
}